// round 17
// baseline (speedup 1.0000x reference)
#include <cuda_runtime.h>
#include <cuda_fp16.h>
#include <cstdint>

#define B_   512
#define T_   1024
#define H_   256
#define NCTA 256
#define NTH  256
#define STG   16384
#define W1OFF 32768
#define W2OFF 57344
#define SGOFF 90112
#define SMEM_DYN (1024 + 110592)

__device__ uint4 g_x_h[8388608];             // [t][512][16 gran] fp16
__device__ uint4 g_w1_h[49152];              // [n'=1024][48 gran] fp16
__device__ uint4 g_w2_h[65536];              // [n'=1024][64 gran]
__device__ uint4 g_h1_h[32768];              // [buf2][512][32 gran] fp16
__device__ uint4 g_h2_h[32768];
__device__ float g_h2f[B_ * H_];
__device__ unsigned g_bcnt[8 * 32];
__device__ unsigned g_bsense[8 * 32];

__device__ __forceinline__ uint32_t sm32(const void* p) {
    uint32_t a;
    asm("{ .reg .u64 t; cvta.to.shared.u64 t, %1; cvt.u32.u64 %0, t; }" : "=r"(a) : "l"(p));
    return a;
}
__device__ __forceinline__ void cp16(uint32_t d, const void* s) {
    asm volatile("cp.async.cg.shared.global [%0], [%1], 16;" :: "r"(d), "l"(s));
}
__device__ __forceinline__ void cp_commit() { asm volatile("cp.async.commit_group;" ::: "memory"); }
template<int N> __device__ __forceinline__ void cp_wait() {
    asm volatile("cp.async.wait_group %0;" :: "n"(N) : "memory");
}
__device__ __forceinline__ void ldsm4(uint32_t& r0, uint32_t& r1, uint32_t& r2, uint32_t& r3, uint32_t a) {
    asm volatile("ldmatrix.sync.aligned.m8n8.x4.shared.b16 {%0,%1,%2,%3}, [%4];"
        : "=r"(r0), "=r"(r1), "=r"(r2), "=r"(r3) : "r"(a));
}
__device__ __forceinline__ void mma16816(float* d, const uint32_t* a, const uint32_t* b) {
    asm volatile("mma.sync.aligned.m16n8k16.row.col.f32.f16.f16.f32 "
        "{%0,%1,%2,%3}, {%4,%5,%6,%7}, {%8,%9}, {%0,%1,%2,%3};"
        : "+f"(d[0]), "+f"(d[1]), "+f"(d[2]), "+f"(d[3])
        : "r"(a[0]), "r"(a[1]), "r"(a[2]), "r"(a[3]), "r"(b[0]), "r"(b[1]));
}
__device__ __forceinline__ float fsig(float x)  { return 1.0f / (1.0f + __expf(-x)); }
__device__ __forceinline__ float ftanh(float x) { return 2.0f / (1.0f + __expf(-2.0f * x)) - 1.0f; }

// per-mt-group barrier: 32 CTAs per group
__device__ __forceinline__ void gbar(int grp, unsigned& sense) {
    unsigned want = sense ^ 1u;
    __threadfence();
    __syncthreads();
    if (threadIdx.x == 0) {
        unsigned* cnt = &g_bcnt[grp * 32];
        unsigned* sns = &g_bsense[grp * 32];
        if (atomicAdd(cnt, 1u) == 31u) {
            *cnt = 0; __threadfence(); atomicExch(sns, want);
        } else {
            while (*(volatile unsigned*)sns != want) __nanosleep(32);
            __threadfence();
        }
    }
    __syncthreads();
    sense = want;
}

// pack 8 floats -> fp16x8 (one uint4)
__device__ __forceinline__ uint4 packh8(const float* v) {
    uint32_t p[4];
    #pragma unroll
    for (int e = 0; e < 4; ++e) {
        __half h0 = __float2half(v[2*e]), h1 = __float2half(v[2*e+1]);
        p[e] = (uint32_t)__half_as_ushort(h0) | ((uint32_t)__half_as_ushort(h1) << 16);
    }
    return make_uint4(p[0], p[1], p[2], p[3]);
}

// copy one 64x128 A tile (fp16) into stage sb: two 8KB sub-tiles, swizzled.
// 1024 granules, 4 per thread. src granule gg of row r at ah + r*astr + gg.
__device__ __forceinline__ void copy_chunk(uint32_t sb, int tid, const uint4* ah, int astr)
{
    #pragma unroll
    for (int i = 0; i < 4; ++i) {
        int idx = i * 256 + tid;
        int r = idx >> 4, gg = idx & 15;
        int sub = gg >> 3, g = gg & 7;
        uint32_t d = sb + (uint32_t)sub * 8192u + (uint32_t)r * 128 + (uint32_t)((g ^ (r & 7)) << 4);
        cp16(d, ah + (size_t)r * astr + gg);
    }
    cp_commit();
}

// compute one K=128 chunk: A from stage sbA, W from persistent wchunk (8KB: 2 sub-tiles of 4KB)
__device__ __forceinline__ void compute_chunk(uint32_t sbA, uint32_t wchunk,
    int lane, int wr, int wc, int kh, float (&acc)[2][2][4])
{
    const int t_ = lane >> 3, l7 = lane & 7;
    const int atq = t_ >> 1, btq = t_ & 1;
    const int arow0 = wr + ((t_ & 1) << 3) + l7;
    const int arow1 = arow0 + 16;
    const int brow  = wc + ((t_ >> 1) << 3) + l7;
    const int kg0 = kh * 8;                       // split-K: this warp's 64-K half

    #pragma unroll
    for (int kb = 0; kb < 4; ++kb) {
        const int kg = kg0 + kb * 2;
        const int sub = kg >> 3, kgl = kg & 7;
        uint32_t ah[2][4], bh[4];
        uint32_t abase = sbA + (uint32_t)sub * 8192u;
        uint32_t ad0 = abase + (uint32_t)arow0 * 128 + (uint32_t)(((kgl + atq) ^ (arow0 & 7)) << 4);
        ldsm4(ah[0][0], ah[0][1], ah[0][2], ah[0][3], ad0);
        uint32_t ad1 = abase + (uint32_t)arow1 * 128 + (uint32_t)(((kgl + atq) ^ (arow1 & 7)) << 4);
        ldsm4(ah[1][0], ah[1][1], ah[1][2], ah[1][3], ad1);
        uint32_t bd = wchunk + (uint32_t)sub * 4096u + (uint32_t)brow * 128
                    + (uint32_t)(((kgl + btq) ^ (brow & 7)) << 4);
        ldsm4(bh[0], bh[1], bh[2], bh[3], bd);
        #pragma unroll
        for (int mb = 0; mb < 2; ++mb)
            #pragma unroll
            for (int nb = 0; nb < 2; ++nb)
                mma16816(acc[mb][nb], ah[mb], &bh[nb * 2]);
    }
}

#define SRC(c) \
    const uint4* sah = ((c) < N0) ? a0h + (c)*16 : a1h + ((c)-N0)*16; \
    int sstr = ((c) < N0) ? S0 : S1;

// 2-stage double buffer: sync, then issue copy(c+1) (overlaps compute(c)), compute(c).
template<int NC, int N0, int S0, int S1>
__device__ __forceinline__ void gemm_main(uint32_t base32, uint32_t wbase, int tid, int lane,
    int wr, int wc, int kh,
    const uint4* a0h, const uint4* a1h, float (&acc)[2][2][4])
{
    #pragma unroll
    for (int c = 0; c < NC; ++c) {
        cp_wait<0>();                     // copy(c) complete (copy(c+1) not yet issued)
        __syncthreads();                  // all warps done with compute(c-1)
        if (c + 1 < NC) {
            SRC(c + 1);
            copy_chunk(base32 + ((c + 1) & 1) * STG, tid, sah, sstr);
        }
        compute_chunk(base32 + (c & 1) * STG, wbase + (uint32_t)c * 8192u,
                      lane, wr, wc, kh, acc);
    }
    __syncthreads();                      // drain before stages are recycled
}

// dh: uint32_t* pre-offset to (buf, row0=mt*64, u32-col jt*4); row stride 128 u32
__device__ __forceinline__ void epilogue(float (&acc)[2][2][4], float* sG, const float* sb,
    float (&cst)[2], uint32_t* dh, float* h2fb,
    int tid, int lane, int wr, int wc, int kh, int jt)
{
    float* sp = sG + kh * 2560;
    #pragma unroll
    for (int mb = 0; mb < 2; ++mb)
        #pragma unroll
        for (int nb = 0; nb < 2; ++nb) {
            int r0 = wr + mb * 16 + (lane >> 2);
            int cc = wc + nb * 8 + (lane & 3) * 2;
            *(float2*)&sp[r0 * 40 + cc]       = make_float2(acc[mb][nb][0], acc[mb][nb][1]);
            *(float2*)&sp[(r0 + 8) * 40 + cc] = make_float2(acc[mb][nb][2], acc[mb][nb][3]);
        }
    __syncthreads();
    const int r = tid >> 2, ju = (tid & 3) * 2;
    float hv[2];
    #pragma unroll
    for (int u = 0; u < 2; ++u) {
        int jj = ju + u;
        float gf = sG[r * 40 + jj]      + sG[2560 + r * 40 + jj]      + sb[jj];
        float gi = sG[r * 40 + 8 + jj]  + sG[2560 + r * 40 + 8 + jj]  + sb[8 + jj];
        float gg = sG[r * 40 + 16 + jj] + sG[2560 + r * 40 + 16 + jj] + sb[16 + jj];
        float go = sG[r * 40 + 24 + jj] + sG[2560 + r * 40 + 24 + jj] + sb[24 + jj];
        float f = fsig(gf), i = fsig(gi), g = ftanh(gg), o = fsig(go);
        float c = f * cst[u] + i * g;
        cst[u] = c;
        hv[u] = o * ftanh(c);
    }
    __half a0 = __float2half(hv[0]), a1 = __float2half(hv[1]);
    dh[r * 128 + (ju >> 1)] = (uint32_t)__half_as_ushort(a0) | ((uint32_t)__half_as_ushort(a1) << 16);
    if (h2fb) {
        h2fb[(size_t)r * 256 + jt * 8 + ju]     = hv[0];
        h2fb[(size_t)r * 256 + jt * 8 + ju + 1] = hv[1];
    }
    __syncthreads();
}

__global__ void __launch_bounds__(NTH, 2)
lstm_mma_kernel(const float* __restrict__ b1, const float* __restrict__ b2,
                const float* __restrict__ Wout, const float* __restrict__ bout,
                float* __restrict__ out)
{
    extern __shared__ uint4 dsm[];
    __shared__ float s_b1[32], s_b2[32];

    const int tid = threadIdx.x, cta = blockIdx.x;
    const int warp = tid >> 5, lane = tid & 31;
    const int mt = cta >> 5, jt = cta & 31;
    const int kh = warp & 1;                       // 2(M:32) x 2(N:16) x 2(K-split)
    const int wr = ((warp >> 1) & 1) * 32, wc = (warp >> 2) * 16;
    uint32_t base32 = (sm32(dsm) + 1023u) & ~1023u;
    float* sG = (float*)((char*)dsm + ((base32 - sm32(dsm)) + SGOFF));

    if (tid < 32) {
        int gate = tid >> 3, u = tid & 7;
        s_b1[tid] = b1[gate * H_ + jt * 8 + u];
        s_b2[tid] = b2[gate * H_ + jt * 8 + u];
    }
    // ---- stage W into persistent smem (once); chunk = 32 rows x 16 granules = 8KB ----
    {
        const uint4* w1h = g_w1_h + (size_t)(jt * 32) * 48;
        const uint4* w2h = g_w2_h + (size_t)(jt * 32) * 64;
        for (int i = tid; i < 1536; i += NTH) {     // W1: 3 chunks x 512 gran
            int c = i >> 9, rg = i & 511, r = rg >> 4, gg = rg & 15;
            int sub = gg >> 3, g = gg & 7;
            cp16(base32 + W1OFF + (uint32_t)c * 8192u + (uint32_t)sub * 4096u
                 + (uint32_t)r * 128 + (uint32_t)((g ^ (r & 7)) << 4),
                 w1h + (size_t)r * 48 + c * 16 + gg);
        }
        for (int i = tid; i < 2048; i += NTH) {     // W2: 4 chunks x 512 gran
            int c = i >> 9, rg = i & 511, r = rg >> 4, gg = rg & 15;
            int sub = gg >> 3, g = gg & 7;
            cp16(base32 + W2OFF + (uint32_t)c * 8192u + (uint32_t)sub * 4096u
                 + (uint32_t)r * 128 + (uint32_t)((g ^ (r & 7)) << 4),
                 w2h + (size_t)r * 64 + c * 16 + gg);
        }
        cp_commit();
    }
    {   // zero this group's h rows
        int i = jt * NTH + tid;
        if (i < 4096) {
            int buf = i >> 11, rr = (i >> 5) & 63, g = i & 31;
            size_t idx = (size_t)buf * 16384 + (size_t)(mt * 64 + rr) * 32 + g;
            uint4 z = make_uint4(0, 0, 0, 0);
            g_h1_h[idx] = z; g_h2_h[idx] = z;
        }
    }
    cp_wait<0>();
    unsigned sense = 0;
    gbar(mt, sense);                               // group barrier #1 (covers W staging)

    float c1[2] = {0.f, 0.f}, c2[2] = {0.f, 0.f};

    for (int p = 0; p < 1025; ++p) {
        const bool do1 = p < 1024, do2 = p > 0;
        float acc1[2][2][4], acc2[2][2][4];

        const int rb1 = (p - 1) & 1;               // h1(p-1) buffer
        const int rb2 = p & 1;                     // h2(p-2) buffer
        const uint4* h1r = g_h1_h + ((size_t)rb1 * 512 + mt * 64) * 32;
        const uint4* h2r = g_h2_h + ((size_t)rb2 * 512 + mt * 64) * 32;

        if (do1) {
            const uint4* xh = g_x_h + ((size_t)p * 512 + mt * 64) * 16;
            #pragma unroll
            for (int mb = 0; mb < 2; ++mb)
                #pragma unroll
                for (int nb = 0; nb < 2; ++nb)
                    #pragma unroll
                    for (int e = 0; e < 4; ++e) acc1[mb][nb][e] = 0.f;
            copy_chunk(base32, tid, xh, 16);       // prologue: chunk 0 (x)
            gemm_main<3,1,16,32>(base32, base32 + W1OFF, tid, lane, wr, wc, kh,
                                 xh, h1r, acc1);
        }
        if (do2) {
            #pragma unroll
            for (int mb = 0; mb < 2; ++mb)
                #pragma unroll
                for (int nb = 0; nb < 2; ++nb)
                    #pragma unroll
                    for (int e = 0; e < 4; ++e) acc2[mb][nb][e] = 0.f;
            copy_chunk(base32, tid, h1r, 32);      // prologue: chunk 0 (h1)
        }
        if (do1) {
            const int wb = p & 1;
            uint32_t* dh = (uint32_t*)(g_h1_h + ((size_t)wb * 512 + mt * 64) * 32) + jt * 4;
            epilogue(acc1, sG, s_b1, c1, dh, (float*)0, tid, lane, wr, wc, kh, jt);
        }
        if (do2) {
            gemm_main<4,2,32,32>(base32, base32 + W2OFF, tid, lane, wr, wc, kh,
                                 h1r, h2r, acc2);
            const int wb = (p - 1) & 1;
            uint32_t* dh = (uint32_t*)(g_h2_h + ((size_t)wb * 512 + mt * 64) * 32) + jt * 4;
            float* hb = (p == 1024) ? g_h2f + (size_t)(mt * 64) * 256 : (float*)0;
            epilogue(acc2, sG, s_b2, c2, dh, hb, tid, lane, wr, wc, kh, jt);
        }
        gbar(mt, sense);                           // group total 1026 barriers (even)
    }

    if (jt == 0 && tid < 64) {
        int row = mt * 64 + tid;
        float s = 0.f;
        #pragma unroll 8
        for (int k = 0; k < H_; ++k) s += g_h2f[(size_t)row * H_ + k] * Wout[k];
        out[row] = s + bout[0];
    }
}

// ---------------- prep: fp16 planes ----------------
__global__ void prep_x_kernel(const float* __restrict__ x) {
    long gid = (long)blockIdx.x * 256 + threadIdx.x;
    int g = (int)(gid & 15);
    int b = (int)((gid >> 4) & 511);
    int t = (int)(gid >> 13);
    const float* src = x + ((size_t)b * 1024 + t) * 128 + g * 8;
    float4 f0 = *(const float4*)src, f1 = *(const float4*)(src + 4);
    float v[8] = {f0.x, f0.y, f0.z, f0.w, f1.x, f1.y, f1.z, f1.w};
    size_t di = ((size_t)t * 512 + b) * 16 + g;
    g_x_h[di] = packh8(v);
}

template<int K, int L>
__global__ void prep_w_kernel(const float* __restrict__ W) {
    uint4* dhi = (L == 1) ? g_w1_h : g_w2_h;
    int gid = blockIdx.x * 256 + threadIdx.x;
    int kg = gid % (K / 8);
    int np = gid / (K / 8);                        // n' = jt*32 + gate*8 + u
    int jt = np >> 5, gate = (np >> 3) & 3, u = np & 7;
    int col = gate * 256 + jt * 8 + u;
    float v[8];
    #pragma unroll
    for (int e = 0; e < 8; ++e) v[e] = W[(size_t)(kg * 8 + e) * 1024 + col];
    dhi[(size_t)np * (K / 8) + kg] = packh8(v);
}

extern "C" void kernel_launch(void* const* d_in, const int* in_sizes, int n_in,
                              void* d_out, int out_size)
{
    (void)in_sizes; (void)n_in; (void)out_size;
    const float* x    = (const float*)d_in[0];
    const float* W1   = (const float*)d_in[1];
    const float* b1   = (const float*)d_in[2];
    const float* W2   = (const float*)d_in[3];
    const float* b2   = (const float*)d_in[4];
    const float* Wout = (const float*)d_in[5];
    const float* bout = (const float*)d_in[6];
    cudaFuncSetAttribute(lstm_mma_kernel, cudaFuncAttributeMaxDynamicSharedMemorySize, SMEM_DYN);
    prep_x_kernel<<<32768, 256>>>(x);
    prep_w_kernel<384, 1><<<192, 256>>>(W1);
    prep_w_kernel<512, 2><<<256, 256>>>(W2);
    lstm_mma_kernel<<<NCTA, NTH, SMEM_DYN>>>(b1, b2, Wout, bout, (float*)d_out);
}